// round 10
// baseline (speedup 1.0000x reference)
#include <cuda_runtime.h>
#include <cuda_fp16.h>
#include <cstdint>

// ---------------------------------------------------------------------------
// Range_Fourier_Net: batched complex DFT == one real GEMM (HMMA mma.sync path).
//   A = [x_r | x_i]            (M=65536, K=512)  fp32 -> fp16 fused into fill
//   B[n][k] from +-W_r/+-W_i   (N=512, K=512)    fp16, prebuilt per launch
//   C = [y_r | y_i]            (M, 512) fp32 -> out[2][M][256]
// 128x128 CTA tile, 4 warps of 64x64, K chunks of 64.
// 3-stage smem pipeline (1 sync/chunk), B cp.async 2 chunks ahead,
// A LDG->cvt->STS 1 chunk ahead staged in registers, ks staggered per warp.
// ---------------------------------------------------------------------------

#define MTOT   65536
#define KTOT   512
#define NBIG   512
#define TILE_M 128
#define TILE_N 128
#define KC     64
#define NCHUNK 8
#define NSTAGE 3

#define SWZ(o) ((o) ^ (((o) >> 3) & 0x70))

// SMEM per stage (bytes): A[128][64]f16 (16K) then B[128][64]f16 (16K)
#define STAGE_BYTES 32768
#define SMEM_BYTES  (NSTAGE * STAGE_BYTES)

__device__ __half g_Wbig[NBIG * KTOT];   // [n][k], K-major rows

// ---------------------------------------------------------------------------
static __device__ __forceinline__ uint32_t smem_u32(const void* p) {
    uint32_t a;
    asm("{ .reg .u64 t; cvta.to.shared.u64 t, %1; cvt.u32.u64 %0, t; }"
        : "=r"(a) : "l"(p));
    return a;
}

#define CP_ASYNC16(dst, src) \
    asm volatile("cp.async.cg.shared.global [%0], [%1], 16;" \
                 :: "r"(dst), "l"(src) : "memory")
#define CP_COMMIT() asm volatile("cp.async.commit_group;" ::: "memory")
#define CP_WAIT1()  asm volatile("cp.async.wait_group 1;" ::: "memory")
#define CP_WAIT0()  asm volatile("cp.async.wait_group 0;" ::: "memory")

#define LDSM_X4(r0, r1, r2, r3, addr)                                        \
    asm volatile("ldmatrix.sync.aligned.m8n8.x4.shared.b16 {%0,%1,%2,%3}, [%4];" \
                 : "=r"(r0), "=r"(r1), "=r"(r2), "=r"(r3) : "r"(addr))

#define MMA16816(d, a0, a1, a2, a3, b0, b1)                                  \
    asm volatile("mma.sync.aligned.m16n8k16.row.col.f32.f16.f16.f32 "        \
                 "{%0,%1,%2,%3}, {%4,%5,%6,%7}, {%8,%9}, {%0,%1,%2,%3};"     \
                 : "+f"((d)[0]), "+f"((d)[1]), "+f"((d)[2]), "+f"((d)[3])    \
                 : "r"(a0), "r"(a1), "r"(a2), "r"(a3), "r"(b0), "r"(b1))

// ---------------------------------------------------------------------------
// Prep: build fp16 B matrix [n][k] (K-major) from W_r/W_i.
//   n<256 (real plane):  B[n] = [  W_r[n] | -W_i[n] ]
//   n>=256 (imag plane): B[n] = [  W_i[n']|  W_r[n']]
// ---------------------------------------------------------------------------
__global__ void prep_w_kernel(const float* __restrict__ wr, const float* __restrict__ wi) {
    int idx = blockIdx.x * blockDim.x + threadIdx.x;
    if (idx >= NBIG * KTOT) return;
    int n = idx >> 9;
    int k = idx & 511;
    float v;
    if (n < 256) {
        v = (k < 256) ? wr[n * 256 + k] : -wi[n * 256 + (k - 256)];
    } else {
        v = (k < 256) ? wi[(n - 256) * 256 + k] : wr[(n - 256) * 256 + (k - 256)];
    }
    g_Wbig[idx] = __float2half_rn(v);
}

// ---------------------------------------------------------------------------
__global__ void __launch_bounds__(128, 2)
dft_gemm_kernel(const float* __restrict__ xr, const float* __restrict__ xi,
                float* __restrict__ out) {
    extern __shared__ char smem[];
    const uint32_t sb = smem_u32(smem);
    const int tid = threadIdx.x;
    const int wid = tid >> 5;
    const int lid = tid & 31;
    const int warp_m = wid & 1;        // 2 warp-rows * 64 m
    const int warp_n = wid >> 1;       // 2 warp-cols * 64 n
    const int n0 = blockIdx.x * TILE_N;   // n fastest: 4 n-tiles of one m-block co-resident
    const int m0 = blockIdx.y * TILE_M;

    float acc[4][8][4];                // [mfrag 16][nfrag 8][reg]
#pragma unroll
    for (int i = 0; i < 4; i++)
#pragma unroll
        for (int j = 0; j < 8; j++)
#pragma unroll
            for (int r = 0; r < 4; r++) acc[i][j][r] = 0.0f;

    // load ownership: 1024 16B-segments per tile, 8 per thread (128 threads)
    const int rlb  = tid >> 3;         // base row, rows rlb + w*16, w=0..7
    const int seg0 = tid & 7;          // 16B segment within 128B row

    // ---- B chunk: 8 cp.async per thread into stage ----
    auto load_B = [&](int c, int stage) {
        const uint32_t b_off = sb + stage * STAGE_BYTES + 16384;
#pragma unroll
        for (int w = 0; w < 8; w++) {
            int rl = rlb + w * 16;
            const __half* g = g_Wbig + (size_t)(n0 + rl) * KTOT + c * KC + seg0 * 8;
            CP_ASYNC16(b_off + SWZ((uint32_t)(rl * 128 + seg0 * 16)), g);
        }
    };

    // ---- A chunk in 2 waves of 4 segments (8 LDG.128 staged in f[8]) ----
    auto ldgA_wave = [&](int c, int w0, float4* f) {
        const float* src = (c < 4) ? xr : xi;
        const int colb = (c & 3) * KC;
#pragma unroll
        for (int q = 0; q < 4; q++) {
            int rl = rlb + (w0 + q) * 16;
            const float4* p = reinterpret_cast<const float4*>(
                src + (size_t)(m0 + rl) * 256 + colb + seg0 * 8);
            f[q * 2] = p[0];
            f[q * 2 + 1] = p[1];
        }
    };
    auto stsA_wave = [&](int stage, int w0, const float4* f) {
#pragma unroll
        for (int q = 0; q < 4; q++) {
            int rl = rlb + (w0 + q) * 16;
            __half2 h0 = __float22half2_rn(make_float2(f[q*2].x, f[q*2].y));
            __half2 h1 = __float22half2_rn(make_float2(f[q*2].z, f[q*2].w));
            __half2 h2 = __float22half2_rn(make_float2(f[q*2+1].x, f[q*2+1].y));
            __half2 h3 = __float22half2_rn(make_float2(f[q*2+1].z, f[q*2+1].w));
            uint4 v;
            v.x = *reinterpret_cast<uint32_t*>(&h0);
            v.y = *reinterpret_cast<uint32_t*>(&h1);
            v.z = *reinterpret_cast<uint32_t*>(&h2);
            v.w = *reinterpret_cast<uint32_t*>(&h3);
            *reinterpret_cast<uint4*>(smem + stage * STAGE_BYTES +
                                      SWZ((uint32_t)(rl * 128 + seg0 * 16))) = v;
        }
    };

    // ldmatrix lane-address components (bytes within tile)
    const uint32_t a_lrow = (uint32_t)(warp_m * 64 + (lid & 15));              // + i*16
    const uint32_t a_lkb  = (uint32_t)((lid >> 4) * 16);                       // + ks*32
    const uint32_t b_lrow = (uint32_t)(warp_n * 64 + (lid >> 4) * 8 + (lid & 7)); // + j*16
    const uint32_t b_lkb  = (uint32_t)(((lid >> 3) & 1) * 16);                 // + ks*32

    auto mma_ks = [&](int ks, uint32_t a_base, uint32_t b_base) {
        uint32_t a[4][4];
#pragma unroll
        for (int i = 0; i < 4; i++) {
            uint32_t addr = a_base + SWZ((a_lrow + i * 16) * 128 + ks * 32 + a_lkb);
            LDSM_X4(a[i][0], a[i][1], a[i][2], a[i][3], addr);
        }
        uint32_t b[16];                 // 8 nfrags x 2 regs
#pragma unroll
        for (int j = 0; j < 4; j++) {
            uint32_t addr = b_base + SWZ((b_lrow + j * 16) * 128 + ks * 32 + b_lkb);
            LDSM_X4(b[j*4+0], b[j*4+1], b[j*4+2], b[j*4+3], addr);
        }
#pragma unroll
        for (int i = 0; i < 4; i++)
#pragma unroll
            for (int j = 0; j < 8; j++)
                MMA16816(acc[i][j], a[i][0], a[i][1], a[i][2], a[i][3],
                         b[j*2+0], b[j*2+1]);
    };

    // ---- prologue: B for chunks 0 and 1 (2 groups), A for chunk 0 ----
    load_B(0, 0);
    CP_COMMIT();
    load_B(1, 1);
    CP_COMMIT();
    {
        float4 f[8];
        ldgA_wave(0, 0, f); stsA_wave(0, 0, f);
        ldgA_wave(0, 4, f); stsA_wave(0, 4, f);
    }

    float4 fst[8];   // A staging for next chunk
    for (int c = 0; c < NCHUNK; c++) {
        // chunk c's B group must be complete. For c<NCHUNK-1 one younger group
        // (chunk c+1) may stay in flight; on the LAST chunk nothing may remain.
        if (c == NCHUNK - 1) CP_WAIT0(); else CP_WAIT1();
        __syncthreads();               // stage c%3 ready; stage (c+1)%3 free (last read c-2)
        const int st  = c % NSTAGE;
        const int sn  = (c + 1) % NSTAGE;
        const uint32_t a_base = sb + st * STAGE_BYTES;
        const uint32_t b_base = a_base + 16384;
        const bool moreA = (c + 1 < NCHUNK);

        if (c + 2 < NCHUNK) {          // B two chunks ahead
            load_B(c + 2, (c + 2) % NSTAGE);
            CP_COMMIT();
        }
        if (moreA) ldgA_wave(c + 1, 0, fst);   // LDG latency overlaps MMAs below

        const int k0 = wid & 3;        // stagger smem regions across warps
        mma_ks(k0, a_base, b_base);
        if (moreA) {
            stsA_wave(sn, 0, fst);
            ldgA_wave(c + 1, 4, fst);
        }
        mma_ks((k0 + 1) & 3, a_base, b_base);
        mma_ks((k0 + 2) & 3, a_base, b_base);
        if (moreA) stsA_wave(sn, 4, fst);
        mma_ks((k0 + 3) & 3, a_base, b_base);
        // no trailing sync: 3-stage ring makes next writes safe after top sync
    }

    // ---- epilogue: direct STG from accumulators ----
    {
        const int plane = (n0 >= 256);
        const int colp = (n0 & 255) + warp_n * 64 + (lid & 3) * 2;
        const int rbase = m0 + warp_m * 64 + (lid >> 2);
        float* outp = out + (size_t)plane * ((size_t)MTOT * 256);
#pragma unroll
        for (int i = 0; i < 4; i++) {
#pragma unroll
            for (int j = 0; j < 8; j++) {
                float2 lo = make_float2(acc[i][j][0], acc[i][j][1]);
                float2 hi = make_float2(acc[i][j][2], acc[i][j][3]);
                size_t r0 = (size_t)(rbase + i * 16) * 256 + colp + j * 8;
                *reinterpret_cast<float2*>(outp + r0) = lo;
                *reinterpret_cast<float2*>(outp + r0 + 8 * 256) = hi;
            }
        }
    }
}

// ---------------------------------------------------------------------------
extern "C" void kernel_launch(void* const* d_in, const int* in_sizes, int n_in,
                              void* d_out, int out_size) {
    const float* xr = (const float*)d_in[0];
    const float* xi = (const float*)d_in[1];
    const float* wr = (const float*)d_in[2];
    const float* wi = (const float*)d_in[3];
    float* out = (float*)d_out;

    prep_w_kernel<<<(NBIG * KTOT) / 256, 256>>>(wr, wi);

    cudaFuncSetAttribute(dft_gemm_kernel,
                         cudaFuncAttributeMaxDynamicSharedMemorySize, SMEM_BYTES);
    dim3 grid(NBIG / TILE_N, MTOT / TILE_M);   // (4, 512), n-tiles fastest
    dft_gemm_kernel<<<grid, 128, SMEM_BYTES>>>(xr, xi, out);
}

// round 14
// speedup vs baseline: 1.4116x; 1.4116x over previous
#include <cuda_runtime.h>
#include <cuda_fp16.h>
#include <cstdint>

// ---------------------------------------------------------------------------
// Range_Fourier_Net: batched complex DFT == one real GEMM (HMMA mma.sync path).
//   A = [x_r | x_i]            (M=65536, K=512)  fp32 -> fp16 fused into fill
//   B[n][k] from +-W_r/+-W_i   (N=512, K=512)    fp16, prebuilt per launch
//   C = [y_r | y_i]            (M, 512) fp32 -> out[2][M][256]
// 128x128 CTA tile, 4 warps of 64x64, K chunks of 64.
// 3-stage smem pipeline (1 sync/chunk), B cp.async 2 chunks ahead,
// A LDG->cvt->STS 1 chunk ahead staged in registers.
// ks order is compile-time (0..3): runtime-staggered ks doubled the dynamic
// instruction count (R10 regression) by defeating immediate folding.
// ---------------------------------------------------------------------------

#define MTOT   65536
#define KTOT   512
#define NBIG   512
#define TILE_M 128
#define TILE_N 128
#define KC     64
#define NCHUNK 8
#define NSTAGE 3

#define SWZ(o) ((o) ^ (((o) >> 3) & 0x70))

// SMEM per stage (bytes): A[128][64]f16 (16K) then B[128][64]f16 (16K)
#define STAGE_BYTES 32768
#define SMEM_BYTES  (NSTAGE * STAGE_BYTES)

__device__ __half g_Wbig[NBIG * KTOT];   // [n][k], K-major rows

// ---------------------------------------------------------------------------
static __device__ __forceinline__ uint32_t smem_u32(const void* p) {
    uint32_t a;
    asm("{ .reg .u64 t; cvta.to.shared.u64 t, %1; cvt.u32.u64 %0, t; }"
        : "=r"(a) : "l"(p));
    return a;
}

#define CP_ASYNC16(dst, src) \
    asm volatile("cp.async.cg.shared.global [%0], [%1], 16;" \
                 :: "r"(dst), "l"(src) : "memory")
#define CP_COMMIT() asm volatile("cp.async.commit_group;" ::: "memory")
#define CP_WAIT1()  asm volatile("cp.async.wait_group 1;" ::: "memory")
#define CP_WAIT0()  asm volatile("cp.async.wait_group 0;" ::: "memory")

#define LDSM_X4(r0, r1, r2, r3, addr)                                        \
    asm volatile("ldmatrix.sync.aligned.m8n8.x4.shared.b16 {%0,%1,%2,%3}, [%4];" \
                 : "=r"(r0), "=r"(r1), "=r"(r2), "=r"(r3) : "r"(addr))

#define MMA16816(d, a0, a1, a2, a3, b0, b1)                                  \
    asm volatile("mma.sync.aligned.m16n8k16.row.col.f32.f16.f16.f32 "        \
                 "{%0,%1,%2,%3}, {%4,%5,%6,%7}, {%8,%9}, {%0,%1,%2,%3};"     \
                 : "+f"((d)[0]), "+f"((d)[1]), "+f"((d)[2]), "+f"((d)[3])    \
                 : "r"(a0), "r"(a1), "r"(a2), "r"(a3), "r"(b0), "r"(b1))

// ---------------------------------------------------------------------------
// Prep: build fp16 B matrix [n][k] (K-major) from W_r/W_i.
//   n<256 (real plane):  B[n] = [  W_r[n] | -W_i[n] ]
//   n>=256 (imag plane): B[n] = [  W_i[n']|  W_r[n']]
// ---------------------------------------------------------------------------
__global__ void prep_w_kernel(const float* __restrict__ wr, const float* __restrict__ wi) {
    int idx = blockIdx.x * blockDim.x + threadIdx.x;
    if (idx >= NBIG * KTOT) return;
    int n = idx >> 9;
    int k = idx & 511;
    float v;
    if (n < 256) {
        v = (k < 256) ? wr[n * 256 + k] : -wi[n * 256 + (k - 256)];
    } else {
        v = (k < 256) ? wi[(n - 256) * 256 + k] : wr[(n - 256) * 256 + (k - 256)];
    }
    g_Wbig[idx] = __float2half_rn(v);
}

// ---------------------------------------------------------------------------
__global__ void __launch_bounds__(128, 2)
dft_gemm_kernel(const float* __restrict__ xr, const float* __restrict__ xi,
                float* __restrict__ out) {
    extern __shared__ char smem[];
    const uint32_t sb = smem_u32(smem);
    const int tid = threadIdx.x;
    const int wid = tid >> 5;
    const int lid = tid & 31;
    const int warp_m = wid & 1;        // 2 warp-rows * 64 m
    const int warp_n = wid >> 1;       // 2 warp-cols * 64 n
    const int n0 = blockIdx.x * TILE_N;   // n fastest: 4 n-tiles of one m-block co-resident
    const int m0 = blockIdx.y * TILE_M;

    float acc[4][8][4];                // [mfrag 16][nfrag 8][reg]
#pragma unroll
    for (int i = 0; i < 4; i++)
#pragma unroll
        for (int j = 0; j < 8; j++)
#pragma unroll
            for (int r = 0; r < 4; r++) acc[i][j][r] = 0.0f;

    // load ownership: 1024 16B-segments per tile, 8 per thread (128 threads)
    const int rlb  = tid >> 3;         // base row, rows rlb + w*16, w=0..7
    const int seg0 = tid & 7;          // 16B segment within 128B row

    // ---- B chunk: 8 cp.async per thread into stage ----
    auto load_B = [&](int c, int stage) {
        const uint32_t b_off = sb + stage * STAGE_BYTES + 16384;
#pragma unroll
        for (int w = 0; w < 8; w++) {
            int rl = rlb + w * 16;
            const __half* g = g_Wbig + (size_t)(n0 + rl) * KTOT + c * KC + seg0 * 8;
            CP_ASYNC16(b_off + SWZ((uint32_t)(rl * 128 + seg0 * 16)), g);
        }
    };

    // ---- A chunk in 2 waves of 4 segments (8 LDG.128 staged in f[8]) ----
    auto ldgA_wave = [&](int c, int w0, float4* f) {
        const float* src = (c < 4) ? xr : xi;
        const int colb = (c & 3) * KC;
#pragma unroll
        for (int q = 0; q < 4; q++) {
            int rl = rlb + (w0 + q) * 16;
            const float4* p = reinterpret_cast<const float4*>(
                src + (size_t)(m0 + rl) * 256 + colb + seg0 * 8);
            f[q * 2] = p[0];
            f[q * 2 + 1] = p[1];
        }
    };
    auto stsA_wave = [&](int stage, int w0, const float4* f) {
#pragma unroll
        for (int q = 0; q < 4; q++) {
            int rl = rlb + (w0 + q) * 16;
            __half2 h0 = __float22half2_rn(make_float2(f[q*2].x, f[q*2].y));
            __half2 h1 = __float22half2_rn(make_float2(f[q*2].z, f[q*2].w));
            __half2 h2 = __float22half2_rn(make_float2(f[q*2+1].x, f[q*2+1].y));
            __half2 h3 = __float22half2_rn(make_float2(f[q*2+1].z, f[q*2+1].w));
            uint4 v;
            v.x = *reinterpret_cast<uint32_t*>(&h0);
            v.y = *reinterpret_cast<uint32_t*>(&h1);
            v.z = *reinterpret_cast<uint32_t*>(&h2);
            v.w = *reinterpret_cast<uint32_t*>(&h3);
            *reinterpret_cast<uint4*>(smem + stage * STAGE_BYTES +
                                      SWZ((uint32_t)(rl * 128 + seg0 * 16))) = v;
        }
    };

    // ldmatrix lane-address components (bytes within tile)
    const uint32_t a_lrow = (uint32_t)(warp_m * 64 + (lid & 15));              // + i*16
    const uint32_t a_lkb  = (uint32_t)((lid >> 4) * 16);                       // + ks*32
    const uint32_t b_lrow = (uint32_t)(warp_n * 64 + (lid >> 4) * 8 + (lid & 7)); // + j*16
    const uint32_t b_lkb  = (uint32_t)(((lid >> 3) & 1) * 16);                 // + ks*32

    auto mma_ks = [&](int ks, uint32_t a_base, uint32_t b_base) {
        uint32_t a[4][4];
#pragma unroll
        for (int i = 0; i < 4; i++) {
            uint32_t addr = a_base + SWZ((a_lrow + i * 16) * 128 + ks * 32 + a_lkb);
            LDSM_X4(a[i][0], a[i][1], a[i][2], a[i][3], addr);
        }
        uint32_t b[16];                 // 8 nfrags x 2 regs
#pragma unroll
        for (int j = 0; j < 4; j++) {
            uint32_t addr = b_base + SWZ((b_lrow + j * 16) * 128 + ks * 32 + b_lkb);
            LDSM_X4(b[j*4+0], b[j*4+1], b[j*4+2], b[j*4+3], addr);
        }
#pragma unroll
        for (int i = 0; i < 4; i++)
#pragma unroll
            for (int j = 0; j < 8; j++)
                MMA16816(acc[i][j], a[i][0], a[i][1], a[i][2], a[i][3],
                         b[j*2+0], b[j*2+1]);
    };

    // ---- prologue: B for chunks 0 and 1 (2 groups), A for chunk 0 ----
    load_B(0, 0);
    CP_COMMIT();
    load_B(1, 1);
    CP_COMMIT();
    {
        float4 f[8];
        ldgA_wave(0, 0, f); stsA_wave(0, 0, f);
        ldgA_wave(0, 4, f); stsA_wave(0, 4, f);
    }

    float4 fst[8];   // A staging for next chunk
    for (int c = 0; c < NCHUNK; c++) {
        // chunk c's B group must be complete. For c<NCHUNK-1 one younger group
        // (chunk c+1) may stay in flight; on the LAST chunk nothing may remain.
        if (c == NCHUNK - 1) CP_WAIT0(); else CP_WAIT1();
        __syncthreads();               // stage c%3 ready; stage (c+1)%3 free (last read c-2)
        const int st  = c % NSTAGE;
        const int sn  = (c + 1) % NSTAGE;
        const uint32_t a_base = sb + st * STAGE_BYTES;
        const uint32_t b_base = a_base + 16384;
        const bool moreA = (c + 1 < NCHUNK);

        if (c + 2 < NCHUNK) {          // B two chunks ahead
            load_B(c + 2, (c + 2) % NSTAGE);
            CP_COMMIT();
        }
        if (moreA) ldgA_wave(c + 1, 0, fst);   // LDG latency overlaps MMAs below

        mma_ks(0, a_base, b_base);
        if (moreA) {
            stsA_wave(sn, 0, fst);
            ldgA_wave(c + 1, 4, fst);
        }
        mma_ks(1, a_base, b_base);
        mma_ks(2, a_base, b_base);
        if (moreA) stsA_wave(sn, 4, fst);
        mma_ks(3, a_base, b_base);
        // no trailing sync: 3-stage ring makes next writes safe after top sync
    }

    // ---- epilogue: direct STG from accumulators ----
    {
        const int plane = (n0 >= 256);
        const int colp = (n0 & 255) + warp_n * 64 + (lid & 3) * 2;
        const int rbase = m0 + warp_m * 64 + (lid >> 2);
        float* outp = out + (size_t)plane * ((size_t)MTOT * 256);
#pragma unroll
        for (int i = 0; i < 4; i++) {
#pragma unroll
            for (int j = 0; j < 8; j++) {
                float2 lo = make_float2(acc[i][j][0], acc[i][j][1]);
                float2 hi = make_float2(acc[i][j][2], acc[i][j][3]);
                size_t r0 = (size_t)(rbase + i * 16) * 256 + colp + j * 8;
                *reinterpret_cast<float2*>(outp + r0) = lo;
                *reinterpret_cast<float2*>(outp + r0 + 8 * 256) = hi;
            }
        }
    }
}

// ---------------------------------------------------------------------------
extern "C" void kernel_launch(void* const* d_in, const int* in_sizes, int n_in,
                              void* d_out, int out_size) {
    const float* xr = (const float*)d_in[0];
    const float* xi = (const float*)d_in[1];
    const float* wr = (const float*)d_in[2];
    const float* wi = (const float*)d_in[3];
    float* out = (float*)d_out;

    prep_w_kernel<<<(NBIG * KTOT) / 256, 256>>>(wr, wi);

    cudaFuncSetAttribute(dft_gemm_kernel,
                         cudaFuncAttributeMaxDynamicSharedMemorySize, SMEM_BYTES);
    dim3 grid(NBIG / TILE_N, MTOT / TILE_M);   // (4, 512), n-tiles fastest
    dft_gemm_kernel<<<grid, 128, SMEM_BYTES>>>(xr, xi, out);
}

// round 15
// speedup vs baseline: 2.9475x; 2.0880x over previous
#include <cuda_runtime.h>
#include <cstdint>

// ---------------------------------------------------------------------------
// Range_Fourier_Net: 256-point complex DFT per row, as a warp-per-row
// radix-2 DIF FFT entirely in registers + warp shuffles.
//   x = x_real + i*x_imag, rows = 64*128*8 = 65536, N = 256
//   y[h] = sum_j x[j] * exp(-2*pi*i*j*h/256)   (reference: x @ W^T, W symmetric)
//   out[0][row][h] = Re y, out[1][row][h] = Im y
//
// Layout: lane t holds 8 complex values at j = t + 32k (k=0..7).
//   DIF stages dj=128,64,32 : within-thread pairs (k, k+4/2/1)
//   DIF stages dj=16,8,4,2,1: shfl.xor stages
// Twiddles: omega^r = W[1][r] = w_real[256+r] / w_imag[256+r]  (exact match
// to reference constants). All twiddle indices compile-time-foldable.
// Output index is bit-reversed: h = rev5(t)*8 + rev3(k)  =>  each lane owns a
// contiguous 8-float span at rev5(t)*8; store as two float4 with k-order
// permuted by rev3. No shared memory, no barriers.
// FLOPs: ~10K/row vs 524K/row for the dense GEMM  ->  FMA/HBM-bound.
// ---------------------------------------------------------------------------

#define MTOT 65536
#define NPT  256
#define RPW  4     // rows per warp

__global__ void __launch_bounds__(256)
fft_kernel(const float* __restrict__ xr, const float* __restrict__ xi,
           const float* __restrict__ wr, const float* __restrict__ wi,
           float* __restrict__ out) {
    const int t   = threadIdx.x & 31;
    const int wid = threadIdx.x >> 5;
    const float* twr = wr + 256;   // W row 1: omega^j, j in [0,256)
    const float* twi = wi + 256;

    // ---- per-thread twiddles, register stages (exponents all < 128) ----
    float T0r[4], T0i[4];                    // stage dj=128: omega^(t+32k), k=0..3
#pragma unroll
    for (int k = 0; k < 4; k++) { T0r[k] = twr[t + 32 * k]; T0i[k] = twi[t + 32 * k]; }
    float T1r[2], T1i[2];                    // stage dj=64: omega^(2t), omega^(2t+64)
    T1r[0] = twr[2 * t];      T1i[0] = twi[2 * t];
    T1r[1] = twr[2 * t + 64]; T1i[1] = twi[2 * t + 64];
    float T2r = twr[4 * t], T2i = twi[4 * t]; // stage dj=32: omega^(4t)

    // ---- unified-butterfly coefficients for shuffle stages h=16,8,4,2 ----
    // out = v*e + p*f ;  a-side (t&h==0): e=f=1 ;  b-side: e=-w, f=w
    float er[4], ei[4], fr[4], fi[4];
#pragma unroll
    for (int s = 0; s < 4; s++) {
        const int h = 16 >> s;
        const int idx = (128 / h) * (t & (h - 1));   // omega^(r*128/h), r = t&(h-1)
        float cr = twr[idx], ci = twi[idx];
        bool bs = (t & h) != 0;
        er[s] = bs ? -cr : 1.0f;  ei[s] = bs ? -ci : 0.0f;
        fr[s] = bs ?  cr : 1.0f;  fi[s] = bs ?  ci : 0.0f;
    }
    const float sgn = (t & 1) ? -1.0f : 1.0f;        // h=1 stage (twiddle = 1)

    const uint32_t rv5 = __brev((uint32_t)t) >> 27;  // rev5(t): output span base /8

    const int warp_global = blockIdx.x * 8 + wid;

    for (int rrow = 0; rrow < RPW; rrow++) {
        const int row = warp_global * RPW + rrow;
        const float* xrp = xr + (size_t)row * NPT;
        const float* xip = xi + (size_t)row * NPT;

        float vr[8], vi[8];
#pragma unroll
        for (int k = 0; k < 8; k++) {                // coalesced 128B per k
            vr[k] = xrp[t + 32 * k];
            vi[k] = xip[t + 32 * k];
        }

        // ---- register stages: dj = 128, 64, 32 ----
#define BF(a, b, cr_, ci_) { float tr = vr[a] - vr[b], ti = vi[a] - vi[b];   \
        vr[a] += vr[b]; vi[a] += vi[b];                                      \
        vr[b] = tr * (cr_) - ti * (ci_); vi[b] = tr * (ci_) + ti * (cr_); }
        BF(0, 4, T0r[0], T0i[0]); BF(1, 5, T0r[1], T0i[1]);
        BF(2, 6, T0r[2], T0i[2]); BF(3, 7, T0r[3], T0i[3]);
        BF(0, 2, T1r[0], T1i[0]); BF(1, 3, T1r[1], T1i[1]);
        BF(4, 6, T1r[0], T1i[0]); BF(5, 7, T1r[1], T1i[1]);
        BF(0, 1, T2r, T2i); BF(2, 3, T2r, T2i);
        BF(4, 5, T2r, T2i); BF(6, 7, T2r, T2i);
#undef BF

        // ---- shuffle stages: dj = 16, 8, 4, 2 (branchless unified butterfly) ----
#pragma unroll
        for (int s = 0; s < 4; s++) {
            const int h = 16 >> s;
#pragma unroll
            for (int k = 0; k < 8; k++) {
                float pr = __shfl_xor_sync(0xffffffffu, vr[k], h);
                float pi = __shfl_xor_sync(0xffffffffu, vi[k], h);
                float nr = vr[k] * er[s] - vi[k] * ei[s] + pr * fr[s] - pi * fi[s];
                float ni = vr[k] * ei[s] + vi[k] * er[s] + pr * fi[s] + pi * fr[s];
                vr[k] = nr; vi[k] = ni;
            }
        }
        // ---- dj = 1 stage: a: v+p ; b: p-v ----
#pragma unroll
        for (int k = 0; k < 8; k++) {
            float pr = __shfl_xor_sync(0xffffffffu, vr[k], 1);
            float pi = __shfl_xor_sync(0xffffffffu, vi[k], 1);
            vr[k] = fmaf(sgn, vr[k], pr);
            vi[k] = fmaf(sgn, vi[k], pi);
        }

        // ---- store: lane t owns y[rev5(t)*8 .. +8), position p holds k=rev3(p) ----
        float* ore = out + (size_t)row * NPT;
        float* oim = out + (size_t)MTOT * NPT + (size_t)row * NPT;
        *reinterpret_cast<float4*>(ore + rv5 * 8)     = make_float4(vr[0], vr[4], vr[2], vr[6]);
        *reinterpret_cast<float4*>(ore + rv5 * 8 + 4) = make_float4(vr[1], vr[5], vr[3], vr[7]);
        *reinterpret_cast<float4*>(oim + rv5 * 8)     = make_float4(vi[0], vi[4], vi[2], vi[6]);
        *reinterpret_cast<float4*>(oim + rv5 * 8 + 4) = make_float4(vi[1], vi[5], vi[3], vi[7]);
    }
}

// ---------------------------------------------------------------------------
extern "C" void kernel_launch(void* const* d_in, const int* in_sizes, int n_in,
                              void* d_out, int out_size) {
    const float* xr = (const float*)d_in[0];
    const float* xi = (const float*)d_in[1];
    const float* wr = (const float*)d_in[2];
    const float* wi = (const float*)d_in[3];
    float* out = (float*)d_out;

    // 65536 rows / (8 warps * RPW rows) = 2048 CTAs
    fft_kernel<<<MTOT / (8 * RPW), 256>>>(xr, xi, wr, wi, out);
}